// round 1
// baseline (speedup 1.0000x reference)
#include <cuda_runtime.h>

#define CIN  128
#define PP   784          // 28*28
#define NPIX 3136         // 4*784
typedef unsigned long long ull;

// ---------------- scratch (device globals; no allocation) ----------------
__device__ float g_y1[CIN * NPIX];        // conv1x1 output, layout [c][q]
__device__ float g_z [CIN * NPIX];        // after adder1x1+bn1+relu
__device__ float g_y3[CIN * NPIX];        // conv3x3 output
__device__ float g_p3[3][CIN * NPIX];     // conv3x3 kh-partials
__device__ float g_p4[3][CIN * NPIX];     // adder3x3 kh-partials (positive L1 sums)

// ---------------- packed f32x2 helpers (Blackwell 2xFP32 path) -----------
__device__ __forceinline__ ull fma2(ull a, ull b, ull c) {
    ull d; asm("fma.rn.f32x2 %0, %1, %2, %3;" : "=l"(d) : "l"(a), "l"(b), "l"(c)); return d;
}
__device__ __forceinline__ ull add2(ull a, ull b) {
    ull d; asm("add.rn.f32x2 %0, %1, %2;" : "=l"(d) : "l"(a), "l"(b)); return d;
}
#define NEG1X2 0xBF800000BF800000ULL   // {-1.0f, -1.0f}
#define ABSM   0x7FFFFFFF7FFFFFFFULL   // clear sign bits of both lanes

__device__ __forceinline__ float lo32(ull v) { return __uint_as_float((unsigned)(v & 0xFFFFFFFFu)); }
__device__ __forceinline__ float hi32(ull v) { return __uint_as_float((unsigned)(v >> 32)); }

// =========================================================================
// Kernel 1: conv1x1  y1[co][q] = sum_ci w1[co][ci] * x[n(q)][ci][p(q)]
// grid (2, 49), 256 threads. Tile 64co x 64px. TC=8, TP=2 (one f32x2).
// =========================================================================
__global__ __launch_bounds__(256) void k1_conv1x1(const float* __restrict__ x,
                                                  const float* __restrict__ w1) {
    __shared__ __align__(16) float  sA[32][64];
    __shared__ __align__(16) float2 sW[32][64];   // duplicated {w,w} pairs

    const int tid = threadIdx.x;
    const int lane = tid & 31, warp = tid >> 5;
    const int coBase = blockIdx.x * 64;
    const int qBase  = blockIdx.y * 64;

    ull acc[8];
#pragma unroll
    for (int i = 0; i < 8; i++) acc[i] = 0ULL;

    for (int ci0 = 0; ci0 < CIN; ci0 += 32) {
#pragma unroll
        for (int k = 0; k < 8; k++) {              // load A tile (gather from NCHW)
            int e = tid + k * 256;
            int ci = e >> 6, j = e & 63;
            int q = qBase + j;
            int n = q / PP, p = q - n * PP;
            sA[ci][j] = x[(n * CIN + ci0 + ci) * PP + p];
        }
#pragma unroll
        for (int k = 0; k < 8; k++) {              // load W tile, duplicated
            int e = tid + k * 256;
            int ci = e >> 6, co = e & 63;
            float v = w1[(coBase + co) * CIN + ci0 + ci];
            sW[ci][co] = make_float2(v, v);
        }
        __syncthreads();
#pragma unroll 8
        for (int ci = 0; ci < 32; ci++) {
            ull a2 = *(const ull*)&sA[ci][lane * 2];
#pragma unroll
            for (int i = 0; i < 8; i++) {
                ull w2 = *(const ull*)&sW[ci][warp * 8 + i];
                acc[i] = fma2(w2, a2, acc[i]);
            }
        }
        __syncthreads();
    }
    const int q = qBase + lane * 2;
#pragma unroll
    for (int i = 0; i < 8; i++) {
        int co = coBase + warp * 8 + i;
        *(ull*)&g_y1[co * NPIX + q] = acc[i];
    }
}

// =========================================================================
// Kernel 2: adder1x1 + BN1 + ReLU.
// z[co][q] = relu( bn1( -sum_ci |y1[ci][q] - wa1[co][ci]| ) )
// Same tiling as k1; a-loads are contiguous ([c][q] layout).
// =========================================================================
__global__ __launch_bounds__(256) void k2_adder1x1(const float* __restrict__ wa1,
                                                    const float* __restrict__ g1,
                                                    const float* __restrict__ b1,
                                                    const float* __restrict__ m1,
                                                    const float* __restrict__ v1) {
    __shared__ __align__(16) float  sA[32][64];
    __shared__ __align__(16) float2 sW[32][64];

    const int tid = threadIdx.x;
    const int lane = tid & 31, warp = tid >> 5;
    const int coBase = blockIdx.x * 64;
    const int qBase  = blockIdx.y * 64;

    ull acc[8];
#pragma unroll
    for (int i = 0; i < 8; i++) acc[i] = 0ULL;

    for (int ci0 = 0; ci0 < CIN; ci0 += 32) {
#pragma unroll
        for (int k = 0; k < 8; k++) {
            int e = tid + k * 256;
            int ci = e >> 6, j = e & 63;
            sA[ci][j] = g_y1[(ci0 + ci) * NPIX + qBase + j];
        }
#pragma unroll
        for (int k = 0; k < 8; k++) {
            int e = tid + k * 256;
            int ci = e >> 6, co = e & 63;
            float v = wa1[(coBase + co) * CIN + ci0 + ci];
            sW[ci][co] = make_float2(v, v);
        }
        __syncthreads();
#pragma unroll 8
        for (int ci = 0; ci < 32; ci++) {
            ull a2 = *(const ull*)&sA[ci][lane * 2];
#pragma unroll
            for (int i = 0; i < 8; i++) {
                ull w2 = *(const ull*)&sW[ci][warp * 8 + i];
                ull t = fma2(w2, NEG1X2, a2) & ABSM;   // |a - w| (AND runs on alu pipe)
                acc[i] = add2(acc[i], t);
            }
        }
        __syncthreads();
    }
    const int q = qBase + lane * 2;
#pragma unroll
    for (int i = 0; i < 8; i++) {
        int co = coBase + warp * 8 + i;
        float scale = g1[co] / sqrtf(v1[co] + 1e-5f);
        float shift = b1[co] - m1[co] * scale;
        float r0 = fmaxf(fmaf(-lo32(acc[i]), scale, shift), 0.f);
        float r1 = fmaxf(fmaf(-hi32(acc[i]), scale, shift), 0.f);
        *(float2*)&g_z[co * NPIX + q] = make_float2(r0, r1);
    }
}

// =========================================================================
// Kernels 3/4: 3x3 conv / adder, split over kh (grid.z = 3 -> 150 CTAs).
// Tile 64co x 128px, TC=8, TP=4 (2 f32x2). Padding handled as zero values
// (which the adder's L1 sum INCLUDES, matching the reference).
// ADDER=false: in = g_z,  out = g_p3[kh], weights w_shift2
// ADDER=true : in = g_y3, out = g_p4[kh], weights w_add2 (stores +S)
// =========================================================================
template <bool ADDER>
__global__ __launch_bounds__(256) void k3x3(const float* __restrict__ wt) {
    __shared__ __align__(16) float  sA[32][128];
    __shared__ __align__(16) float2 sW[32][64];

    const int tid = threadIdx.x;
    const int lane = tid & 31, warp = tid >> 5;
    const int coBase = blockIdx.x * 64;
    const int qBase  = blockIdx.y * 128;
    const int kh = blockIdx.z;

    const float* __restrict__ in = ADDER ? g_y3 : g_z;
    float* __restrict__ out = ADDER ? g_p4[kh] : g_p3[kh];

    ull acc[8][2];
#pragma unroll
    for (int i = 0; i < 8; i++) { acc[i][0] = 0ULL; acc[i][1] = 0ULL; }

    for (int kw = 0; kw < 3; kw++) {
        for (int ci0 = 0; ci0 < CIN; ci0 += 32) {
#pragma unroll
            for (int k = 0; k < 16; k++) {         // shifted A tile, zero-padded
                int e = tid + k * 256;
                int ci = e >> 7, j = e & 127;
                int q = qBase + j;
                float val = 0.f;
                if (q < NPIX) {
                    int n = q / PP, p = q - n * PP;
                    int h = p / 28, w = p - h * 28;
                    int hh = h + kh - 1, ww = w + kw - 1;
                    if ((unsigned)hh < 28u && (unsigned)ww < 28u)
                        val = in[(ci0 + ci) * NPIX + n * PP + hh * 28 + ww];
                }
                sA[ci][j] = val;
            }
#pragma unroll
            for (int k = 0; k < 8; k++) {          // W tile, duplicated
                int e = tid + k * 256;
                int ci = e >> 6, co = e & 63;
                float v = wt[((coBase + co) * CIN + ci0 + ci) * 9 + kh * 3 + kw];
                sW[ci][co] = make_float2(v, v);
            }
            __syncthreads();
#pragma unroll 4
            for (int ci = 0; ci < 32; ci++) {
                ull a0 = *(const ull*)&sA[ci][lane * 4];
                ull a1 = *(const ull*)&sA[ci][lane * 4 + 2];
#pragma unroll
                for (int i = 0; i < 8; i++) {
                    ull w2 = *(const ull*)&sW[ci][warp * 8 + i];
                    if (ADDER) {
                        ull t0 = fma2(w2, NEG1X2, a0) & ABSM;
                        ull t1 = fma2(w2, NEG1X2, a1) & ABSM;
                        acc[i][0] = add2(acc[i][0], t0);
                        acc[i][1] = add2(acc[i][1], t1);
                    } else {
                        acc[i][0] = fma2(w2, a0, acc[i][0]);
                        acc[i][1] = fma2(w2, a1, acc[i][1]);
                    }
                }
            }
            __syncthreads();
        }
    }
    const int q = qBase + lane * 4;
    if (q < NPIX) {
#pragma unroll
        for (int i = 0; i < 8; i++) {
            int co = coBase + warp * 8 + i;
            *(ull*)&out[co * NPIX + q]     = acc[i][0];
            *(ull*)&out[co * NPIX + q + 2] = acc[i][1];
        }
    }
}

// Combine conv3x3 kh-partials: y3 = p0 + p1 + p2.  grid 392 x 256 x vec4.
__global__ __launch_bounds__(256) void kcombine() {
    int i = (blockIdx.x * 256 + threadIdx.x) * 4;
    float4 a = *(const float4*)&g_p3[0][i];
    float4 b = *(const float4*)&g_p3[1][i];
    float4 c = *(const float4*)&g_p3[2][i];
    float4 r;
    r.x = a.x + b.x + c.x; r.y = a.y + b.y + c.y;
    r.z = a.z + b.z + c.z; r.w = a.w + b.w + c.w;
    *(float4*)&g_y3[i] = r;
}

// Epilogue: out = relu( relu(bn2(-(S0+S1+S2))) + x ), NCHW output.
__device__ __forceinline__ float epi1(float S, float xv, float scale, float shift) {
    float v = fmaxf(fmaf(-S, scale, shift), 0.f);
    return fmaxf(v + xv, 0.f);
}
__global__ __launch_bounds__(256) void kepi(const float* __restrict__ x,
                                             const float* __restrict__ g2,
                                             const float* __restrict__ b2,
                                             const float* __restrict__ m2,
                                             const float* __restrict__ v2,
                                             float* __restrict__ out) {
    int base = (blockIdx.x * 256 + threadIdx.x) * 4;
    int c = base / NPIX;
    int q = base - c * NPIX;
    int n = q / PP, p = q - n * PP;
    float scale = g2[c] / sqrtf(v2[c] + 1e-5f);
    float shift = b2[c] - m2[c] * scale;
    float4 s0 = *(const float4*)&g_p4[0][base];
    float4 s1 = *(const float4*)&g_p4[1][base];
    float4 s2 = *(const float4*)&g_p4[2][base];
    int xi = (n * CIN + c) * PP + p;
    float4 xr = *(const float4*)&x[xi];
    float4 r;
    r.x = epi1(s0.x + s1.x + s2.x, xr.x, scale, shift);
    r.y = epi1(s0.y + s1.y + s2.y, xr.y, scale, shift);
    r.z = epi1(s0.z + s1.z + s2.z, xr.z, scale, shift);
    r.w = epi1(s0.w + s1.w + s2.w, xr.w, scale, shift);
    *(float4*)&out[xi] = r;
}

// =========================================================================
extern "C" void kernel_launch(void* const* d_in, const int* in_sizes, int n_in,
                              void* d_out, int out_size) {
    const float* x   = (const float*)d_in[0];
    const float* w1  = (const float*)d_in[1];
    const float* wa1 = (const float*)d_in[2];
    const float* g1  = (const float*)d_in[3];
    const float* b1  = (const float*)d_in[4];
    const float* m1  = (const float*)d_in[5];
    const float* v1  = (const float*)d_in[6];
    const float* w2  = (const float*)d_in[7];
    const float* wa2 = (const float*)d_in[8];
    const float* g2  = (const float*)d_in[9];
    const float* b2  = (const float*)d_in[10];
    const float* m2  = (const float*)d_in[11];
    const float* v2  = (const float*)d_in[12];
    float* out = (float*)d_out;

    k1_conv1x1  <<<dim3(2, 49),    256>>>(x, w1);
    k2_adder1x1 <<<dim3(2, 49),    256>>>(wa1, g1, b1, m1, v1);
    k3x3<false> <<<dim3(2, 25, 3), 256>>>(w2);
    kcombine    <<<392,            256>>>();
    k3x3<true>  <<<dim3(2, 25, 3), 256>>>(wa2);
    kepi        <<<392,            256>>>(x, g2, b2, m2, v2, out);
}

// round 2
// speedup vs baseline: 1.0704x; 1.0704x over previous
#include <cuda_runtime.h>

#define CIN  128
#define PP   784          // 28*28
#define NPIX 3136         // 4*784
typedef unsigned long long ull;

// ---------------- scratch (device globals; no allocation) ----------------
__device__ __align__(16) float g_y1[CIN * NPIX];     // conv1x1 out, [c][q]
__device__ __align__(16) float g_z [CIN * NPIX];     // after adder1x1+bn1+relu
__device__ __align__(16) float g_p3[3][CIN * NPIX];  // conv3x3 kh-partials
__device__ __align__(16) float g_p4[3][CIN * NPIX];  // adder3x3 kh-partials (+S)

// ---------------- packed f32x2 helpers -----------------------------------
__device__ __forceinline__ ull fma2(ull a, ull b, ull c) {
    ull d; asm("fma.rn.f32x2 %0, %1, %2, %3;" : "=l"(d) : "l"(a), "l"(b), "l"(c)); return d;
}
__device__ __forceinline__ ull add2(ull a, ull b) {
    ull d; asm("add.rn.f32x2 %0, %1, %2;" : "=l"(d) : "l"(a), "l"(b)); return d;
}
#define NEG1X2 0xBF800000BF800000ULL
#define ABSM   0x7FFFFFFF7FFFFFFFULL
__device__ __forceinline__ float lo32(ull v) { return __uint_as_float((unsigned)(v & 0xFFFFFFFFu)); }
__device__ __forceinline__ float hi32(ull v) { return __uint_as_float((unsigned)(v >> 32)); }

// =========================================================================
// k1: conv1x1.  CTA 64co x 64px, 256 thr, thread tile 4co x 4px.
// grid (2, 49). Register-prefetch pipelined, ci chunk 16 (8 stages).
// =========================================================================
__global__ __launch_bounds__(256) void k1_conv1x1(const float* __restrict__ x,
                                                  const float* __restrict__ w1) {
    __shared__ __align__(16) float  sA[16][64];
    __shared__ __align__(16) float2 sW[16][64];
    const int tid = threadIdx.x;
    const int col = tid & 15;          // px group (4 px)
    const int row = tid >> 4;          // co group (4 co)
    const int coBase = blockIdx.x * 64;
    const int qBase  = blockIdx.y * 64;

    ull acc[4][2];
#pragma unroll
    for (int i = 0; i < 4; i++) { acc[i][0] = 0; acc[i][1] = 0; }

    float aReg[4], wReg[4];
    auto loadStage = [&](int s) {
        int ci0 = s << 4;
#pragma unroll
        for (int k = 0; k < 4; k++) {
            int e = k * 256 + tid;
            int ci = e >> 6, j = e & 63;
            int q = qBase + j;
            int n = q / PP, p = q - n * PP;
            aReg[k] = x[(n * CIN + ci0 + ci) * PP + p];
        }
#pragma unroll
        for (int k = 0; k < 4; k++) {
            int e = k * 256 + tid;
            int ci = e >> 6, co = e & 63;
            wReg[k] = w1[(coBase + co) * CIN + ci0 + ci];
        }
    };
    auto storeStage = [&]() {
#pragma unroll
        for (int k = 0; k < 4; k++) { int e = k * 256 + tid; sA[e >> 6][e & 63] = aReg[k]; }
#pragma unroll
        for (int k = 0; k < 4; k++) { int e = k * 256 + tid; float v = wReg[k]; sW[e >> 6][e & 63] = make_float2(v, v); }
    };

    loadStage(0);
    for (int s = 0; s < 8; s++) {
        __syncthreads();
        storeStage();
        __syncthreads();
        if (s < 7) loadStage(s + 1);
#pragma unroll
        for (int ci = 0; ci < 16; ci++) {
            ulonglong2 av = *(const ulonglong2*)&sA[ci][col * 4];
            ulonglong2 w01 = *(const ulonglong2*)&sW[ci][row * 4];
            ulonglong2 w23 = *(const ulonglong2*)&sW[ci][row * 4 + 2];
            acc[0][0] = fma2(w01.x, av.x, acc[0][0]); acc[0][1] = fma2(w01.x, av.y, acc[0][1]);
            acc[1][0] = fma2(w01.y, av.x, acc[1][0]); acc[1][1] = fma2(w01.y, av.y, acc[1][1]);
            acc[2][0] = fma2(w23.x, av.x, acc[2][0]); acc[2][1] = fma2(w23.x, av.y, acc[2][1]);
            acc[3][0] = fma2(w23.y, av.x, acc[3][0]); acc[3][1] = fma2(w23.y, av.y, acc[3][1]);
        }
    }
    const int q = qBase + col * 4;
#pragma unroll
    for (int i = 0; i < 4; i++) {
        int co = coBase + row * 4 + i;
        *(ull*)&g_y1[co * NPIX + q]     = acc[i][0];
        *(ull*)&g_y1[co * NPIX + q + 2] = acc[i][1];
    }
}

// =========================================================================
// k2: adder1x1 + BN1 + ReLU. Same shape as k1; A reads are contiguous.
// =========================================================================
__global__ __launch_bounds__(256) void k2_adder1x1(const float* __restrict__ wa1,
                                                    const float* __restrict__ g1,
                                                    const float* __restrict__ b1,
                                                    const float* __restrict__ m1,
                                                    const float* __restrict__ v1) {
    __shared__ __align__(16) float  sA[16][64];
    __shared__ __align__(16) float2 sW[16][64];
    const int tid = threadIdx.x;
    const int col = tid & 15, row = tid >> 4;
    const int coBase = blockIdx.x * 64;
    const int qBase  = blockIdx.y * 64;

    ull acc[4][2];
#pragma unroll
    for (int i = 0; i < 4; i++) { acc[i][0] = 0; acc[i][1] = 0; }

    float aReg[4], wReg[4];
    auto loadStage = [&](int s) {
        int ci0 = s << 4;
#pragma unroll
        for (int k = 0; k < 4; k++) {
            int e = k * 256 + tid;
            int ci = e >> 6, j = e & 63;
            aReg[k] = g_y1[(ci0 + ci) * NPIX + qBase + j];
        }
#pragma unroll
        for (int k = 0; k < 4; k++) {
            int e = k * 256 + tid;
            int ci = e >> 6, co = e & 63;
            wReg[k] = wa1[(coBase + co) * CIN + ci0 + ci];
        }
    };
    auto storeStage = [&]() {
#pragma unroll
        for (int k = 0; k < 4; k++) { int e = k * 256 + tid; sA[e >> 6][e & 63] = aReg[k]; }
#pragma unroll
        for (int k = 0; k < 4; k++) { int e = k * 256 + tid; float v = wReg[k]; sW[e >> 6][e & 63] = make_float2(v, v); }
    };

    loadStage(0);
    for (int s = 0; s < 8; s++) {
        __syncthreads();
        storeStage();
        __syncthreads();
        if (s < 7) loadStage(s + 1);
#pragma unroll
        for (int ci = 0; ci < 16; ci++) {
            ulonglong2 av = *(const ulonglong2*)&sA[ci][col * 4];
            ulonglong2 w01 = *(const ulonglong2*)&sW[ci][row * 4];
            ulonglong2 w23 = *(const ulonglong2*)&sW[ci][row * 4 + 2];
            acc[0][0] = add2(acc[0][0], fma2(w01.x, NEG1X2, av.x) & ABSM);
            acc[0][1] = add2(acc[0][1], fma2(w01.x, NEG1X2, av.y) & ABSM);
            acc[1][0] = add2(acc[1][0], fma2(w01.y, NEG1X2, av.x) & ABSM);
            acc[1][1] = add2(acc[1][1], fma2(w01.y, NEG1X2, av.y) & ABSM);
            acc[2][0] = add2(acc[2][0], fma2(w23.x, NEG1X2, av.x) & ABSM);
            acc[2][1] = add2(acc[2][1], fma2(w23.x, NEG1X2, av.y) & ABSM);
            acc[3][0] = add2(acc[3][0], fma2(w23.y, NEG1X2, av.x) & ABSM);
            acc[3][1] = add2(acc[3][1], fma2(w23.y, NEG1X2, av.y) & ABSM);
        }
    }
    const int q = qBase + col * 4;
#pragma unroll
    for (int i = 0; i < 4; i++) {
        int co = coBase + row * 4 + i;
        float scale = g1[co] / sqrtf(v1[co] + 1e-5f);
        float shift = b1[co] - m1[co] * scale;
        float r0 = fmaxf(fmaf(-lo32(acc[i][0]), scale, shift), 0.f);
        float r1 = fmaxf(fmaf(-hi32(acc[i][0]), scale, shift), 0.f);
        float r2 = fmaxf(fmaf(-lo32(acc[i][1]), scale, shift), 0.f);
        float r3 = fmaxf(fmaf(-hi32(acc[i][1]), scale, shift), 0.f);
        *(float4*)&g_z[co * NPIX + q] = make_float4(r0, r1, r2, r3);
    }
}

// =========================================================================
// k3 / k4: 3x3 conv / adder, kh-split (grid.z=3 -> 150 CTAs).
// CTA 64co x 128px, 256 thr, thread tile 8co x 4px (warp = 1 co-row x 32 px:
// weight LDS fully broadcast, A one LDS.128). Precomputed gather table.
// ADDER folds the conv partial sum (p0+p1+p2) into its A staging.
// =========================================================================
template <bool ADDER>
__global__ __launch_bounds__(256) void k3x3(const float* __restrict__ wt) {
    __shared__ __align__(16) float  sA[16][128];
    __shared__ __align__(16) float2 sW[16][64];
    __shared__ int sIdx[3][128];

    const int tid = threadIdx.x;
    const int col = tid & 31;          // px group (4 px)
    const int row = tid >> 5;          // co group (8 co) == warp id
    const int coBase = blockIdx.x * 64;
    const int qBase  = blockIdx.y * 128;
    const int kh = blockIdx.z;

    if (tid < 128) {
        int q = qBase + tid;
#pragma unroll
        for (int kw = 0; kw < 3; kw++) {
            int idx = -1;
            if (q < NPIX) {
                int n = q / PP, p = q - n * PP;
                int h = p / 28, w = p - h * 28;
                int hh = h + kh - 1, ww = w + kw - 1;
                if ((unsigned)hh < 28u && (unsigned)ww < 28u) idx = n * PP + hh * 28 + ww;
            }
            sIdx[kw][tid] = idx;
        }
    }
    __syncthreads();

    ull acc[8][2];
#pragma unroll
    for (int i = 0; i < 8; i++) { acc[i][0] = 0; acc[i][1] = 0; }

    float aReg[8][3];   // [3] used only when ADDER (partial fold); else [0]
    float wReg[4];
    auto loadStage = [&](int s) {
        int kw = s >> 3, ci0 = (s & 7) << 4;
#pragma unroll
        for (int k = 0; k < 8; k++) {
            int e = k * 256 + tid;
            int ci = e >> 7, j = e & 127;
            int idx = sIdx[kw][j];
            if (idx >= 0) {
                int off = (ci0 + ci) * NPIX + idx;
                if (ADDER) {
                    aReg[k][0] = g_p3[0][off];
                    aReg[k][1] = g_p3[1][off];
                    aReg[k][2] = g_p3[2][off];
                } else {
                    aReg[k][0] = g_z[off];
                }
            } else {
                aReg[k][0] = 0.f;
                if (ADDER) { aReg[k][1] = 0.f; aReg[k][2] = 0.f; }
            }
        }
#pragma unroll
        for (int k = 0; k < 4; k++) {
            int e = k * 256 + tid;
            int ci = e >> 6, co = e & 63;
            wReg[k] = wt[((coBase + co) * CIN + ci0 + ci) * 9 + kh * 3 + kw];
        }
    };
    auto storeStage = [&]() {
#pragma unroll
        for (int k = 0; k < 8; k++) {
            int e = k * 256 + tid;
            float v = aReg[k][0];
            if (ADDER) v += aReg[k][1] + aReg[k][2];
            sA[e >> 7][e & 127] = v;
        }
#pragma unroll
        for (int k = 0; k < 4; k++) {
            int e = k * 256 + tid;
            float v = wReg[k];
            sW[e >> 6][e & 63] = make_float2(v, v);
        }
    };

    loadStage(0);
    for (int s = 0; s < 24; s++) {
        __syncthreads();
        storeStage();
        __syncthreads();
        if (s < 23) loadStage(s + 1);
#pragma unroll
        for (int ci = 0; ci < 16; ci++) {
            ulonglong2 av = *(const ulonglong2*)&sA[ci][col * 4];
#pragma unroll
            for (int jj = 0; jj < 4; jj++) {
                ulonglong2 wp = *(const ulonglong2*)&sW[ci][row * 8 + jj * 2];
                int i0 = jj * 2, i1 = jj * 2 + 1;
                if (ADDER) {
                    acc[i0][0] = add2(acc[i0][0], fma2(wp.x, NEG1X2, av.x) & ABSM);
                    acc[i0][1] = add2(acc[i0][1], fma2(wp.x, NEG1X2, av.y) & ABSM);
                    acc[i1][0] = add2(acc[i1][0], fma2(wp.y, NEG1X2, av.x) & ABSM);
                    acc[i1][1] = add2(acc[i1][1], fma2(wp.y, NEG1X2, av.y) & ABSM);
                } else {
                    acc[i0][0] = fma2(wp.x, av.x, acc[i0][0]);
                    acc[i0][1] = fma2(wp.x, av.y, acc[i0][1]);
                    acc[i1][0] = fma2(wp.y, av.x, acc[i1][0]);
                    acc[i1][1] = fma2(wp.y, av.y, acc[i1][1]);
                }
            }
        }
    }
    const int q = qBase + col * 4;
    if (q < NPIX) {
        float* __restrict__ out = ADDER ? g_p4[kh] : g_p3[kh];
#pragma unroll
        for (int i = 0; i < 8; i++) {
            int co = coBase + row * 8 + i;
            *(ull*)&out[co * NPIX + q]     = acc[i][0];
            *(ull*)&out[co * NPIX + q + 2] = acc[i][1];
        }
    }
}

// =========================================================================
// Epilogue: out = relu( relu(bn2(-(S0+S1+S2))) + x ), NCHW output.
// =========================================================================
__device__ __forceinline__ float epi1(float S, float xv, float scale, float shift) {
    float v = fmaxf(fmaf(-S, scale, shift), 0.f);
    return fmaxf(v + xv, 0.f);
}
__global__ __launch_bounds__(256) void kepi(const float* __restrict__ x,
                                             const float* __restrict__ g2,
                                             const float* __restrict__ b2,
                                             const float* __restrict__ m2,
                                             const float* __restrict__ v2,
                                             float* __restrict__ out) {
    int base = (blockIdx.x * 256 + threadIdx.x) * 4;
    int c = base / NPIX;
    int q = base - c * NPIX;
    int n = q / PP, p = q - n * PP;
    float scale = g2[c] / sqrtf(v2[c] + 1e-5f);
    float shift = b2[c] - m2[c] * scale;
    float4 s0 = *(const float4*)&g_p4[0][base];
    float4 s1 = *(const float4*)&g_p4[1][base];
    float4 s2 = *(const float4*)&g_p4[2][base];
    int xi = (n * CIN + c) * PP + p;
    float4 xr = *(const float4*)&x[xi];
    float4 r;
    r.x = epi1(s0.x + s1.x + s2.x, xr.x, scale, shift);
    r.y = epi1(s0.y + s1.y + s2.y, xr.y, scale, shift);
    r.z = epi1(s0.z + s1.z + s2.z, xr.z, scale, shift);
    r.w = epi1(s0.w + s1.w + s2.w, xr.w, scale, shift);
    *(float4*)&out[xi] = r;
}

// =========================================================================
extern "C" void kernel_launch(void* const* d_in, const int* in_sizes, int n_in,
                              void* d_out, int out_size) {
    const float* x   = (const float*)d_in[0];
    const float* w1  = (const float*)d_in[1];
    const float* wa1 = (const float*)d_in[2];
    const float* g1  = (const float*)d_in[3];
    const float* b1  = (const float*)d_in[4];
    const float* m1  = (const float*)d_in[5];
    const float* v1  = (const float*)d_in[6];
    const float* w2  = (const float*)d_in[7];
    const float* wa2 = (const float*)d_in[8];
    const float* g2  = (const float*)d_in[9];
    const float* b2  = (const float*)d_in[10];
    const float* m2  = (const float*)d_in[11];
    const float* v2  = (const float*)d_in[12];
    float* out = (float*)d_out;

    k1_conv1x1  <<<dim3(2, 49),    256>>>(x, w1);
    k2_adder1x1 <<<dim3(2, 49),    256>>>(wa1, g1, b1, m1, v1);
    k3x3<false> <<<dim3(2, 25, 3), 256>>>(w2);
    k3x3<true>  <<<dim3(2, 25, 3), 256>>>(wa2);
    kepi        <<<392,            256>>>(x, g2, b2, m2, v2, out);
}

// round 3
// speedup vs baseline: 1.3982x; 1.3062x over previous
#include <cuda_runtime.h>

#define CIN  128
#define PP   784          // 28*28
#define NPIX 3136         // 4*784
typedef unsigned long long ull;

// ---------------- scratch (device globals; no allocation) ----------------
__device__ __align__(16) float g_y1[CIN * NPIX];     // conv1x1 out, [c][q]
__device__ __align__(16) float g_z [CIN * NPIX];     // after adder1x1+bn1+relu
__device__ __align__(16) float g_p3[3][CIN * NPIX];  // conv3x3 kh-partials
__device__ __align__(16) float g_p4[3][CIN * NPIX];  // adder3x3 kh-partials (+S)

// ---------------- packed f32x2 helpers -----------------------------------
__device__ __forceinline__ ull fma2(ull a, ull b, ull c) {
    ull d; asm("fma.rn.f32x2 %0, %1, %2, %3;" : "=l"(d) : "l"(a), "l"(b), "l"(c)); return d;
}
__device__ __forceinline__ ull add2(ull a, ull b) {
    ull d; asm("add.rn.f32x2 %0, %1, %2;" : "=l"(d) : "l"(a), "l"(b)); return d;
}
#define NEG1X2 0xBF800000BF800000ULL
#define ABSM   0x7FFFFFFF7FFFFFFFULL
__device__ __forceinline__ float lo32(ull v) { return __uint_as_float((unsigned)(v & 0xFFFFFFFFu)); }
__device__ __forceinline__ float hi32(ull v) { return __uint_as_float((unsigned)(v >> 32)); }

// =========================================================================
// k1: conv1x1.  CTA 64co x 64px, 256 thr, tile 4co x 4px. grid (2,49).
// Double-buffered smem, ONE barrier per stage. 8 stages of 16 ci.
// =========================================================================
__global__ __launch_bounds__(256) void k1_conv1x1(const float* __restrict__ x,
                                                  const float* __restrict__ w1) {
    __shared__ __align__(16) float  sA[2][16][64];
    __shared__ __align__(16) float2 sW[2][16][64];
    const int tid = threadIdx.x;
    const int col = tid & 15, row = tid >> 4;
    const int coBase = blockIdx.x * 64;
    const int qBase  = blockIdx.y * 64;

    ull acc[4][2];
#pragma unroll
    for (int i = 0; i < 4; i++) { acc[i][0] = 0; acc[i][1] = 0; }

    float aReg[4], wReg[4];
    auto ldg = [&](int s) {
        int ci0 = s << 4;
#pragma unroll
        for (int k = 0; k < 4; k++) {
            int e = k * 256 + tid;
            int ci = e >> 6, j = e & 63;
            int q = qBase + j;
            int n = q / PP, p = q - n * PP;
            aReg[k] = x[(n * CIN + ci0 + ci) * PP + p];
        }
#pragma unroll
        for (int k = 0; k < 4; k++) {
            int e = k * 256 + tid;
            wReg[k] = w1[(coBase + (e & 63)) * CIN + ci0 + (e >> 6)];
        }
    };
    auto sts = [&](int b) {
#pragma unroll
        for (int k = 0; k < 4; k++) { int e = k * 256 + tid; sA[b][e >> 6][e & 63] = aReg[k]; }
#pragma unroll
        for (int k = 0; k < 4; k++) { int e = k * 256 + tid; float v = wReg[k]; sW[b][e >> 6][e & 63] = make_float2(v, v); }
    };

    ldg(0); sts(0); __syncthreads();
    for (int s = 0; s < 8; s++) {
        int b = s & 1;
        if (s < 7) ldg(s + 1);
#pragma unroll
        for (int ci = 0; ci < 16; ci++) {
            ulonglong2 av = *(const ulonglong2*)&sA[b][ci][col * 4];
            ulonglong2 wp = *(const ulonglong2*)&sW[b][ci][row * 4];
            ulonglong2 wq = *(const ulonglong2*)&sW[b][ci][row * 4 + 2];
            acc[0][0] = fma2(wp.x, av.x, acc[0][0]); acc[0][1] = fma2(wp.x, av.y, acc[0][1]);
            acc[1][0] = fma2(wp.y, av.x, acc[1][0]); acc[1][1] = fma2(wp.y, av.y, acc[1][1]);
            acc[2][0] = fma2(wq.x, av.x, acc[2][0]); acc[2][1] = fma2(wq.x, av.y, acc[2][1]);
            acc[3][0] = fma2(wq.y, av.x, acc[3][0]); acc[3][1] = fma2(wq.y, av.y, acc[3][1]);
        }
        if (s < 7) sts(b ^ 1);
        __syncthreads();
    }
    const int q = qBase + col * 4;
#pragma unroll
    for (int i = 0; i < 4; i++) {
        int co = coBase + row * 4 + i;
        *(ull*)&g_y1[co * NPIX + q]     = acc[i][0];
        *(ull*)&g_y1[co * NPIX + q + 2] = acc[i][1];
    }
}

// =========================================================================
// k2: adder1x1 + BN1 + ReLU. Same structure; A reads contiguous from g_y1.
// =========================================================================
__global__ __launch_bounds__(256) void k2_adder1x1(const float* __restrict__ wa1,
                                                    const float* __restrict__ g1,
                                                    const float* __restrict__ b1,
                                                    const float* __restrict__ m1,
                                                    const float* __restrict__ v1) {
    __shared__ __align__(16) float  sA[2][16][64];
    __shared__ __align__(16) float2 sW[2][16][64];
    const int tid = threadIdx.x;
    const int col = tid & 15, row = tid >> 4;
    const int coBase = blockIdx.x * 64;
    const int qBase  = blockIdx.y * 64;

    ull acc[4][2];
#pragma unroll
    for (int i = 0; i < 4; i++) { acc[i][0] = 0; acc[i][1] = 0; }

    float aReg[4], wReg[4];
    auto ldg = [&](int s) {
        int ci0 = s << 4;
#pragma unroll
        for (int k = 0; k < 4; k++) {
            int e = k * 256 + tid;
            aReg[k] = g_y1[(ci0 + (e >> 6)) * NPIX + qBase + (e & 63)];
        }
#pragma unroll
        for (int k = 0; k < 4; k++) {
            int e = k * 256 + tid;
            wReg[k] = wa1[(coBase + (e & 63)) * CIN + ci0 + (e >> 6)];
        }
    };
    auto sts = [&](int b) {
#pragma unroll
        for (int k = 0; k < 4; k++) { int e = k * 256 + tid; sA[b][e >> 6][e & 63] = aReg[k]; }
#pragma unroll
        for (int k = 0; k < 4; k++) { int e = k * 256 + tid; float v = wReg[k]; sW[b][e >> 6][e & 63] = make_float2(v, v); }
    };

    ldg(0); sts(0); __syncthreads();
    for (int s = 0; s < 8; s++) {
        int b = s & 1;
        if (s < 7) ldg(s + 1);
#pragma unroll
        for (int ci = 0; ci < 16; ci++) {
            ulonglong2 av = *(const ulonglong2*)&sA[b][ci][col * 4];
            ulonglong2 wp = *(const ulonglong2*)&sW[b][ci][row * 4];
            ulonglong2 wq = *(const ulonglong2*)&sW[b][ci][row * 4 + 2];
            acc[0][0] = add2(acc[0][0], fma2(wp.x, NEG1X2, av.x) & ABSM);
            acc[0][1] = add2(acc[0][1], fma2(wp.x, NEG1X2, av.y) & ABSM);
            acc[1][0] = add2(acc[1][0], fma2(wp.y, NEG1X2, av.x) & ABSM);
            acc[1][1] = add2(acc[1][1], fma2(wp.y, NEG1X2, av.y) & ABSM);
            acc[2][0] = add2(acc[2][0], fma2(wq.x, NEG1X2, av.x) & ABSM);
            acc[2][1] = add2(acc[2][1], fma2(wq.x, NEG1X2, av.y) & ABSM);
            acc[3][0] = add2(acc[3][0], fma2(wq.y, NEG1X2, av.x) & ABSM);
            acc[3][1] = add2(acc[3][1], fma2(wq.y, NEG1X2, av.y) & ABSM);
        }
        if (s < 7) sts(b ^ 1);
        __syncthreads();
    }
    const int q = qBase + col * 4;
#pragma unroll
    for (int i = 0; i < 4; i++) {
        int co = coBase + row * 4 + i;
        float scale = g1[co] / sqrtf(v1[co] + 1e-5f);
        float shift = b1[co] - m1[co] * scale;
        float r0 = fmaxf(fmaf(-lo32(acc[i][0]), scale, shift), 0.f);
        float r1 = fmaxf(fmaf(-hi32(acc[i][0]), scale, shift), 0.f);
        float r2 = fmaxf(fmaf(-lo32(acc[i][1]), scale, shift), 0.f);
        float r3 = fmaxf(fmaf(-hi32(acc[i][1]), scale, shift), 0.f);
        *(float4*)&g_z[co * NPIX + q] = make_float4(r0, r1, r2, r3);
    }
}

// =========================================================================
// k3/k4: 3x3 conv / adder, kh-split. CTA 64co x 64px, 256 thr, tile 4co x 4px.
// grid (2, 49, 3) = 294 CTAs -> 2 CTAs/SM (16 warps). Double-buffered smem,
// one barrier per stage, 24 stages (kw x ci-chunk16). Gather via precomputed
// per-CTA index table. ADDER folds p0+p1+p2 into its A staging.
// =========================================================================
template <bool ADDER>
__global__ __launch_bounds__(256) void k3x3(const float* __restrict__ wt) {
    __shared__ __align__(16) float  sA[2][16][64];
    __shared__ __align__(16) float2 sW[2][16][64];
    __shared__ int sIdx[3][64];

    const int tid = threadIdx.x;
    const int col = tid & 15, row = tid >> 4;
    const int coBase = blockIdx.x * 64;
    const int qBase  = blockIdx.y * 64;
    const int kh = blockIdx.z;

    if (tid < 64) {
        int q = qBase + tid;
        int n = q / PP, p = q - n * PP;
        int h = p / 28, w = p - h * 28;
#pragma unroll
        for (int kw = 0; kw < 3; kw++) {
            int hh = h + kh - 1, ww = w + kw - 1;
            sIdx[kw][tid] = ((unsigned)hh < 28u && (unsigned)ww < 28u)
                          ? (n * PP + hh * 28 + ww) : -1;
        }
    }
    __syncthreads();

    ull acc[4][2];
#pragma unroll
    for (int i = 0; i < 4; i++) { acc[i][0] = 0; acc[i][1] = 0; }

    float aReg[4], wReg[4];
    auto ldg = [&](int s) {
        int kw = s >> 3, ci0 = (s & 7) << 4;
#pragma unroll
        for (int k = 0; k < 4; k++) {
            int e = k * 256 + tid;
            int ci = ci0 + (e >> 6);
            int idx = sIdx[kw][e & 63];
            float v = 0.f;
            if (idx >= 0) {
                int off = ci * NPIX + idx;
                if (ADDER) v = g_p3[0][off] + g_p3[1][off] + g_p3[2][off];
                else       v = g_z[off];
            }
            aReg[k] = v;
        }
#pragma unroll
        for (int k = 0; k < 4; k++) {
            int e = k * 256 + tid;
            wReg[k] = wt[((coBase + (e & 63)) * CIN + ci0 + (e >> 6)) * 9 + kh * 3 + kw];
        }
    };
    auto sts = [&](int b) {
#pragma unroll
        for (int k = 0; k < 4; k++) { int e = k * 256 + tid; sA[b][e >> 6][e & 63] = aReg[k]; }
#pragma unroll
        for (int k = 0; k < 4; k++) { int e = k * 256 + tid; float v = wReg[k]; sW[b][e >> 6][e & 63] = make_float2(v, v); }
    };

    ldg(0); sts(0); __syncthreads();
    for (int s = 0; s < 24; s++) {
        int b = s & 1;
        if (s < 23) ldg(s + 1);
#pragma unroll
        for (int ci = 0; ci < 16; ci++) {
            ulonglong2 av = *(const ulonglong2*)&sA[b][ci][col * 4];
            ulonglong2 wp = *(const ulonglong2*)&sW[b][ci][row * 4];
            ulonglong2 wq = *(const ulonglong2*)&sW[b][ci][row * 4 + 2];
            if (ADDER) {
                acc[0][0] = add2(acc[0][0], fma2(wp.x, NEG1X2, av.x) & ABSM);
                acc[0][1] = add2(acc[0][1], fma2(wp.x, NEG1X2, av.y) & ABSM);
                acc[1][0] = add2(acc[1][0], fma2(wp.y, NEG1X2, av.x) & ABSM);
                acc[1][1] = add2(acc[1][1], fma2(wp.y, NEG1X2, av.y) & ABSM);
                acc[2][0] = add2(acc[2][0], fma2(wq.x, NEG1X2, av.x) & ABSM);
                acc[2][1] = add2(acc[2][1], fma2(wq.x, NEG1X2, av.y) & ABSM);
                acc[3][0] = add2(acc[3][0], fma2(wq.y, NEG1X2, av.x) & ABSM);
                acc[3][1] = add2(acc[3][1], fma2(wq.y, NEG1X2, av.y) & ABSM);
            } else {
                acc[0][0] = fma2(wp.x, av.x, acc[0][0]); acc[0][1] = fma2(wp.x, av.y, acc[0][1]);
                acc[1][0] = fma2(wp.y, av.x, acc[1][0]); acc[1][1] = fma2(wp.y, av.y, acc[1][1]);
                acc[2][0] = fma2(wq.x, av.x, acc[2][0]); acc[2][1] = fma2(wq.x, av.y, acc[2][1]);
                acc[3][0] = fma2(wq.y, av.x, acc[3][0]); acc[3][1] = fma2(wq.y, av.y, acc[3][1]);
            }
        }
        if (s < 23) sts(b ^ 1);
        __syncthreads();
    }
    const int q = qBase + col * 4;
    float* __restrict__ out = ADDER ? g_p4[kh] : g_p3[kh];
#pragma unroll
    for (int i = 0; i < 4; i++) {
        int co = coBase + row * 4 + i;
        *(ull*)&out[co * NPIX + q]     = acc[i][0];
        *(ull*)&out[co * NPIX + q + 2] = acc[i][1];
    }
}

// =========================================================================
// Epilogue: out = relu( relu(bn2(-(S0+S1+S2))) + x ), NCHW output.
// =========================================================================
__device__ __forceinline__ float epi1(float S, float xv, float scale, float shift) {
    float v = fmaxf(fmaf(-S, scale, shift), 0.f);
    return fmaxf(v + xv, 0.f);
}
__global__ __launch_bounds__(256) void kepi(const float* __restrict__ x,
                                             const float* __restrict__ g2,
                                             const float* __restrict__ b2,
                                             const float* __restrict__ m2,
                                             const float* __restrict__ v2,
                                             float* __restrict__ out) {
    int base = (blockIdx.x * 256 + threadIdx.x) * 4;
    int c = base / NPIX;
    int q = base - c * NPIX;
    int n = q / PP, p = q - n * PP;
    float scale = g2[c] / sqrtf(v2[c] + 1e-5f);
    float shift = b2[c] - m2[c] * scale;
    float4 s0 = *(const float4*)&g_p4[0][base];
    float4 s1 = *(const float4*)&g_p4[1][base];
    float4 s2 = *(const float4*)&g_p4[2][base];
    int xi = (n * CIN + c) * PP + p;
    float4 xr = *(const float4*)&x[xi];
    float4 r;
    r.x = epi1(s0.x + s1.x + s2.x, xr.x, scale, shift);
    r.y = epi1(s0.y + s1.y + s2.y, xr.y, scale, shift);
    r.z = epi1(s0.z + s1.z + s2.z, xr.z, scale, shift);
    r.w = epi1(s0.w + s1.w + s2.w, xr.w, scale, shift);
    *(float4*)&out[xi] = r;
}

// =========================================================================
extern "C" void kernel_launch(void* const* d_in, const int* in_sizes, int n_in,
                              void* d_out, int out_size) {
    const float* x   = (const float*)d_in[0];
    const float* w1  = (const float*)d_in[1];
    const float* wa1 = (const float*)d_in[2];
    const float* g1  = (const float*)d_in[3];
    const float* b1  = (const float*)d_in[4];
    const float* m1  = (const float*)d_in[5];
    const float* v1  = (const float*)d_in[6];
    const float* w2  = (const float*)d_in[7];
    const float* wa2 = (const float*)d_in[8];
    const float* g2  = (const float*)d_in[9];
    const float* b2  = (const float*)d_in[10];
    const float* m2  = (const float*)d_in[11];
    const float* v2  = (const float*)d_in[12];
    float* out = (float*)d_out;

    k1_conv1x1  <<<dim3(2, 49),    256>>>(x, w1);
    k2_adder1x1 <<<dim3(2, 49),    256>>>(wa1, g1, b1, m1, v1);
    k3x3<false> <<<dim3(2, 49, 3), 256>>>(w2);
    k3x3<true>  <<<dim3(2, 49, 3), 256>>>(wa2);
    kepi        <<<392,            256>>>(x, g2, b2, m2, v2, out);
}

// round 4
// speedup vs baseline: 1.9700x; 1.4090x over previous
#include <cuda_runtime.h>

#define CIN  128
#define PP   784          // 28*28
#define NPIX 3136         // 4*784
typedef unsigned long long ull;

// ---------------- scratch (device globals; no allocation) ----------------
__device__ __align__(16) float g_y1p[2][CIN * NPIX];  // conv1x1 ci-half partials
__device__ __align__(16) float g_s1p[2][CIN * NPIX];  // adder1x1 ci-half partial L1 sums
__device__ __align__(16) float g_z  [CIN * NPIX];     // after bn1+relu
__device__ __align__(16) float g_p3 [6][CIN * NPIX];  // conv3x3 (kh,ciHalf) partials
__device__ __align__(16) float g_y3 [CIN * NPIX];     // conv3x3 combined
__device__ __align__(16) float g_p4 [6][CIN * NPIX];  // adder3x3 partials (+S)
// duplicated-transposed weights: [ci][co] as {w,w}
__device__ __align__(16) float2 g_w1d [CIN * CIN];
__device__ __align__(16) float2 g_wa1d[CIN * CIN];
__device__ __align__(16) float2 g_w2d [9][CIN * CIN];
__device__ __align__(16) float2 g_wa2d[9][CIN * CIN];

// ---------------- packed f32x2 helpers -----------------------------------
__device__ __forceinline__ ull fma2(ull a, ull b, ull c) {
    ull d; asm("fma.rn.f32x2 %0, %1, %2, %3;" : "=l"(d) : "l"(a), "l"(b), "l"(c)); return d;
}
__device__ __forceinline__ ull add2(ull a, ull b) {
    ull d; asm("add.rn.f32x2 %0, %1, %2;" : "=l"(d) : "l"(a), "l"(b)); return d;
}
#define NEG1X2 0xBF800000BF800000ULL
#define ABSM   0x7FFFFFFF7FFFFFFFULL

// =========================================================================
// k0: weight prep. w*d[ci][co] = {w[co][ci], w[co][ci]}; 3x3 also per tap.
// =========================================================================
__global__ __launch_bounds__(256) void kprep(const float* __restrict__ w1,
                                             const float* __restrict__ wa1,
                                             const float* __restrict__ w2,
                                             const float* __restrict__ wa2) {
    int i = blockIdx.x * 256 + threadIdx.x;     // 64 blocks -> 16384
    int ci = i >> 7, co = i & 127;
    float v = w1[co * CIN + ci];  g_w1d [ci * CIN + co] = make_float2(v, v);
    v = wa1[co * CIN + ci];       g_wa1d[ci * CIN + co] = make_float2(v, v);
#pragma unroll
    for (int t = 0; t < 9; t++) {
        v = w2 [(co * CIN + ci) * 9 + t]; g_w2d [t][ci * CIN + co] = make_float2(v, v);
        v = wa2[(co * CIN + ci) * 9 + t]; g_wa2d[t][ci * CIN + co] = make_float2(v, v);
    }
}

// =========================================================================
// k1: conv1x1 ci-half partial. grid (2,49,2). CTA 64co x 64px, tile 4x4.
// 4 stages of 16 ci, double-buffered, one barrier per stage.
// =========================================================================
__global__ __launch_bounds__(256) void k1_conv1x1(const float* __restrict__ x) {
    __shared__ __align__(16) float  sA[2][16][64];
    __shared__ __align__(16) float2 sW[2][16][64];
    const int tid = threadIdx.x;
    const int col = tid & 15, row = tid >> 4;
    const int coBase = blockIdx.x * 64;
    const int qBase  = blockIdx.y * 64;
    const int ciBase = blockIdx.z * 64;

    ull acc[4][2];
#pragma unroll
    for (int i = 0; i < 4; i++) { acc[i][0] = 0; acc[i][1] = 0; }

    float aReg[4]; float2 wReg[4];
    auto ldg = [&](int s) {
        int ci0 = ciBase + (s << 4);
#pragma unroll
        for (int k = 0; k < 4; k++) {
            int e = k * 256 + tid;
            int q = qBase + (e & 63);
            int n = q / PP, p = q - n * PP;
            aReg[k] = x[(n * CIN + ci0 + (e >> 6)) * PP + p];
        }
#pragma unroll
        for (int k = 0; k < 4; k++) {
            int e = k * 256 + tid;
            wReg[k] = g_w1d[(ci0 + (e >> 6)) * CIN + coBase + (e & 63)];
        }
    };
    auto sts = [&](int b) {
#pragma unroll
        for (int k = 0; k < 4; k++) { int e = k * 256 + tid; sA[b][e >> 6][e & 63] = aReg[k]; }
#pragma unroll
        for (int k = 0; k < 4; k++) { int e = k * 256 + tid; sW[b][e >> 6][e & 63] = wReg[k]; }
    };

    ldg(0); sts(0); __syncthreads();
    for (int s = 0; s < 4; s++) {
        int b = s & 1;
        if (s < 3) ldg(s + 1);
#pragma unroll
        for (int ci = 0; ci < 16; ci++) {
            ulonglong2 av = *(const ulonglong2*)&sA[b][ci][col * 4];
            ulonglong2 wp = *(const ulonglong2*)&sW[b][ci][row * 4];
            ulonglong2 wq = *(const ulonglong2*)&sW[b][ci][row * 4 + 2];
            acc[0][0] = fma2(wp.x, av.x, acc[0][0]); acc[0][1] = fma2(wp.x, av.y, acc[0][1]);
            acc[1][0] = fma2(wp.y, av.x, acc[1][0]); acc[1][1] = fma2(wp.y, av.y, acc[1][1]);
            acc[2][0] = fma2(wq.x, av.x, acc[2][0]); acc[2][1] = fma2(wq.x, av.y, acc[2][1]);
            acc[3][0] = fma2(wq.y, av.x, acc[3][0]); acc[3][1] = fma2(wq.y, av.y, acc[3][1]);
        }
        if (s < 3) sts(b ^ 1);
        __syncthreads();
    }
    const int q = qBase + col * 4;
    float* __restrict__ out = g_y1p[blockIdx.z];
#pragma unroll
    for (int i = 0; i < 4; i++) {
        int co = coBase + row * 4 + i;
        *(ull*)&out[co * NPIX + q]     = acc[i][0];
        *(ull*)&out[co * NPIX + q + 2] = acc[i][1];
    }
}

// =========================================================================
// k2: adder1x1 ci-half partial L1 sums (no BN). A = y1p[0]+y1p[1] at load.
// grid (2,49,2).
// =========================================================================
__global__ __launch_bounds__(256) void k2_adder1x1() {
    __shared__ __align__(16) float  sA[2][16][64];
    __shared__ __align__(16) float2 sW[2][16][64];
    const int tid = threadIdx.x;
    const int col = tid & 15, row = tid >> 4;
    const int coBase = blockIdx.x * 64;
    const int qBase  = blockIdx.y * 64;
    const int ciBase = blockIdx.z * 64;

    ull acc[4][2];
#pragma unroll
    for (int i = 0; i < 4; i++) { acc[i][0] = 0; acc[i][1] = 0; }

    float aReg[4]; float2 wReg[4];
    auto ldg = [&](int s) {
        int ci0 = ciBase + (s << 4);
#pragma unroll
        for (int k = 0; k < 4; k++) {
            int e = k * 256 + tid;
            int off = (ci0 + (e >> 6)) * NPIX + qBase + (e & 63);
            aReg[k] = g_y1p[0][off] + g_y1p[1][off];
        }
#pragma unroll
        for (int k = 0; k < 4; k++) {
            int e = k * 256 + tid;
            wReg[k] = g_wa1d[(ci0 + (e >> 6)) * CIN + coBase + (e & 63)];
        }
    };
    auto sts = [&](int b) {
#pragma unroll
        for (int k = 0; k < 4; k++) { int e = k * 256 + tid; sA[b][e >> 6][e & 63] = aReg[k]; }
#pragma unroll
        for (int k = 0; k < 4; k++) { int e = k * 256 + tid; sW[b][e >> 6][e & 63] = wReg[k]; }
    };

    ldg(0); sts(0); __syncthreads();
    for (int s = 0; s < 4; s++) {
        int b = s & 1;
        if (s < 3) ldg(s + 1);
#pragma unroll
        for (int ci = 0; ci < 16; ci++) {
            ulonglong2 av = *(const ulonglong2*)&sA[b][ci][col * 4];
            ulonglong2 wp = *(const ulonglong2*)&sW[b][ci][row * 4];
            ulonglong2 wq = *(const ulonglong2*)&sW[b][ci][row * 4 + 2];
            acc[0][0] = add2(acc[0][0], fma2(wp.x, NEG1X2, av.x) & ABSM);
            acc[0][1] = add2(acc[0][1], fma2(wp.x, NEG1X2, av.y) & ABSM);
            acc[1][0] = add2(acc[1][0], fma2(wp.y, NEG1X2, av.x) & ABSM);
            acc[1][1] = add2(acc[1][1], fma2(wp.y, NEG1X2, av.y) & ABSM);
            acc[2][0] = add2(acc[2][0], fma2(wq.x, NEG1X2, av.x) & ABSM);
            acc[2][1] = add2(acc[2][1], fma2(wq.x, NEG1X2, av.y) & ABSM);
            acc[3][0] = add2(acc[3][0], fma2(wq.y, NEG1X2, av.x) & ABSM);
            acc[3][1] = add2(acc[3][1], fma2(wq.y, NEG1X2, av.y) & ABSM);
        }
        if (s < 3) sts(b ^ 1);
        __syncthreads();
    }
    const int q = qBase + col * 4;
    float* __restrict__ out = g_s1p[blockIdx.z];
#pragma unroll
    for (int i = 0; i < 4; i++) {
        int co = coBase + row * 4 + i;
        *(ull*)&out[co * NPIX + q]     = acc[i][0];
        *(ull*)&out[co * NPIX + q + 2] = acc[i][1];
    }
}

// kz: z = relu(bn1(-(s0+s1)))
__global__ __launch_bounds__(256) void kz(const float* __restrict__ g1,
                                           const float* __restrict__ b1,
                                           const float* __restrict__ m1,
                                           const float* __restrict__ v1) {
    int base = (blockIdx.x * 256 + threadIdx.x) * 4;
    int c = base / NPIX;
    float scale = g1[c] / sqrtf(v1[c] + 1e-5f);
    float shift = b1[c] - m1[c] * scale;
    float4 a = *(const float4*)&g_s1p[0][base];
    float4 b = *(const float4*)&g_s1p[1][base];
    float4 r;
    r.x = fmaxf(fmaf(-(a.x + b.x), scale, shift), 0.f);
    r.y = fmaxf(fmaf(-(a.y + b.y), scale, shift), 0.f);
    r.z = fmaxf(fmaf(-(a.z + b.z), scale, shift), 0.f);
    r.w = fmaxf(fmaf(-(a.w + b.w), scale, shift), 0.f);
    *(float4*)&g_z[base] = r;
}

// =========================================================================
// k3/k4: 3x3 conv / adder. grid (2,49,6): z = kh*2 + ciHalf -> 588 CTAs
// (4 CTAs/SM, 32 warps). 12 stages (kw x 4 ci-chunks of 16), double-buffered.
// =========================================================================
template <bool ADDER>
__global__ __launch_bounds__(256) void k3x3() {
    __shared__ __align__(16) float  sA[2][16][64];
    __shared__ __align__(16) float2 sW[2][16][64];
    __shared__ int sIdx[3][64];

    const int tid = threadIdx.x;
    const int col = tid & 15, row = tid >> 4;
    const int coBase = blockIdx.x * 64;
    const int qBase  = blockIdx.y * 64;
    const int kh     = blockIdx.z >> 1;
    const int ciBase = (blockIdx.z & 1) * 64;

    if (tid < 64) {
        int q = qBase + tid;
        int n = q / PP, p = q - n * PP;
        int h = p / 28, w = p - h * 28;
#pragma unroll
        for (int kw = 0; kw < 3; kw++) {
            int hh = h + kh - 1, ww = w + kw - 1;
            sIdx[kw][tid] = ((unsigned)hh < 28u && (unsigned)ww < 28u)
                          ? (n * PP + hh * 28 + ww) : -1;
        }
    }
    __syncthreads();

    ull acc[4][2];
#pragma unroll
    for (int i = 0; i < 4; i++) { acc[i][0] = 0; acc[i][1] = 0; }

    const float* __restrict__ in = ADDER ? g_y3 : g_z;
    const float2 (* __restrict__ wd)[CIN * CIN] = ADDER ? g_wa2d : g_w2d;

    float aReg[4]; float2 wReg[4];
    auto ldg = [&](int s) {
        int kw = s >> 2, ci0 = ciBase + ((s & 3) << 4);
#pragma unroll
        for (int k = 0; k < 4; k++) {
            int e = k * 256 + tid;
            int idx = sIdx[kw][e & 63];
            aReg[k] = (idx >= 0) ? in[(ci0 + (e >> 6)) * NPIX + idx] : 0.f;
        }
        const float2* __restrict__ wslice = wd[kh * 3 + kw];
#pragma unroll
        for (int k = 0; k < 4; k++) {
            int e = k * 256 + tid;
            wReg[k] = wslice[(ci0 + (e >> 6)) * CIN + coBase + (e & 63)];
        }
    };
    auto sts = [&](int b) {
#pragma unroll
        for (int k = 0; k < 4; k++) { int e = k * 256 + tid; sA[b][e >> 6][e & 63] = aReg[k]; }
#pragma unroll
        for (int k = 0; k < 4; k++) { int e = k * 256 + tid; sW[b][e >> 6][e & 63] = wReg[k]; }
    };

    ldg(0); sts(0); __syncthreads();
    for (int s = 0; s < 12; s++) {
        int b = s & 1;
        if (s < 11) ldg(s + 1);
#pragma unroll
        for (int ci = 0; ci < 16; ci++) {
            ulonglong2 av = *(const ulonglong2*)&sA[b][ci][col * 4];
            ulonglong2 wp = *(const ulonglong2*)&sW[b][ci][row * 4];
            ulonglong2 wq = *(const ulonglong2*)&sW[b][ci][row * 4 + 2];
            if (ADDER) {
                acc[0][0] = add2(acc[0][0], fma2(wp.x, NEG1X2, av.x) & ABSM);
                acc[0][1] = add2(acc[0][1], fma2(wp.x, NEG1X2, av.y) & ABSM);
                acc[1][0] = add2(acc[1][0], fma2(wp.y, NEG1X2, av.x) & ABSM);
                acc[1][1] = add2(acc[1][1], fma2(wp.y, NEG1X2, av.y) & ABSM);
                acc[2][0] = add2(acc[2][0], fma2(wq.x, NEG1X2, av.x) & ABSM);
                acc[2][1] = add2(acc[2][1], fma2(wq.x, NEG1X2, av.y) & ABSM);
                acc[3][0] = add2(acc[3][0], fma2(wq.y, NEG1X2, av.x) & ABSM);
                acc[3][1] = add2(acc[3][1], fma2(wq.y, NEG1X2, av.y) & ABSM);
            } else {
                acc[0][0] = fma2(wp.x, av.x, acc[0][0]); acc[0][1] = fma2(wp.x, av.y, acc[0][1]);
                acc[1][0] = fma2(wp.y, av.x, acc[1][0]); acc[1][1] = fma2(wp.y, av.y, acc[1][1]);
                acc[2][0] = fma2(wq.x, av.x, acc[2][0]); acc[2][1] = fma2(wq.x, av.y, acc[2][1]);
                acc[3][0] = fma2(wq.y, av.x, acc[3][0]); acc[3][1] = fma2(wq.y, av.y, acc[3][1]);
            }
        }
        if (s < 11) sts(b ^ 1);
        __syncthreads();
    }
    const int q = qBase + col * 4;
    float* __restrict__ out = ADDER ? g_p4[blockIdx.z] : g_p3[blockIdx.z];
#pragma unroll
    for (int i = 0; i < 4; i++) {
        int co = coBase + row * 4 + i;
        *(ull*)&out[co * NPIX + q]     = acc[i][0];
        *(ull*)&out[co * NPIX + q + 2] = acc[i][1];
    }
}

// ky: y3 = sum of 6 conv partials
__global__ __launch_bounds__(256) void ky() {
    int i = (blockIdx.x * 256 + threadIdx.x) * 4;
    float4 s = *(const float4*)&g_p3[0][i];
#pragma unroll
    for (int t = 1; t < 6; t++) {
        float4 a = *(const float4*)&g_p3[t][i];
        s.x += a.x; s.y += a.y; s.z += a.z; s.w += a.w;
    }
    *(float4*)&g_y3[i] = s;
}

// Epilogue: out = relu( relu(bn2(-(S))) + x ), S = sum of 6 adder partials.
__device__ __forceinline__ float epi1(float S, float xv, float scale, float shift) {
    float v = fmaxf(fmaf(-S, scale, shift), 0.f);
    return fmaxf(v + xv, 0.f);
}
__global__ __launch_bounds__(256) void kepi(const float* __restrict__ x,
                                             const float* __restrict__ g2,
                                             const float* __restrict__ b2,
                                             const float* __restrict__ m2,
                                             const float* __restrict__ v2,
                                             float* __restrict__ out) {
    int base = (blockIdx.x * 256 + threadIdx.x) * 4;
    int c = base / NPIX;
    int q = base - c * NPIX;
    int n = q / PP, p = q - n * PP;
    float scale = g2[c] / sqrtf(v2[c] + 1e-5f);
    float shift = b2[c] - m2[c] * scale;
    float4 s = *(const float4*)&g_p4[0][base];
#pragma unroll
    for (int t = 1; t < 6; t++) {
        float4 a = *(const float4*)&g_p4[t][base];
        s.x += a.x; s.y += a.y; s.z += a.z; s.w += a.w;
    }
    int xi = (n * CIN + c) * PP + p;
    float4 xr = *(const float4*)&x[xi];
    float4 r;
    r.x = epi1(s.x, xr.x, scale, shift);
    r.y = epi1(s.y, xr.y, scale, shift);
    r.z = epi1(s.z, xr.z, scale, shift);
    r.w = epi1(s.w, xr.w, scale, shift);
    *(float4*)&out[xi] = r;
}

// =========================================================================
extern "C" void kernel_launch(void* const* d_in, const int* in_sizes, int n_in,
                              void* d_out, int out_size) {
    const float* x   = (const float*)d_in[0];
    const float* w1  = (const float*)d_in[1];
    const float* wa1 = (const float*)d_in[2];
    const float* g1  = (const float*)d_in[3];
    const float* b1  = (const float*)d_in[4];
    const float* m1  = (const float*)d_in[5];
    const float* v1  = (const float*)d_in[6];
    const float* w2  = (const float*)d_in[7];
    const float* wa2 = (const float*)d_in[8];
    const float* g2  = (const float*)d_in[9];
    const float* b2  = (const float*)d_in[10];
    const float* m2  = (const float*)d_in[11];
    const float* v2  = (const float*)d_in[12];
    float* out = (float*)d_out;

    kprep       <<<64,             256>>>(w1, wa1, w2, wa2);
    k1_conv1x1  <<<dim3(2, 49, 2), 256>>>(x);
    k2_adder1x1 <<<dim3(2, 49, 2), 256>>>();
    kz          <<<392,            256>>>(g1, b1, m1, v1);
    k3x3<false> <<<dim3(2, 49, 6), 256>>>();
    ky          <<<392,            256>>>();
    k3x3<true>  <<<dim3(2, 49, 6), 256>>>();
    kepi        <<<392,            256>>>(x, g2, b2, m2, v2, out);
}

// round 5
// speedup vs baseline: 1.9812x; 1.0057x over previous
#include <cuda_runtime.h>

#define CIN  128
#define PP   784          // 28*28
#define NPIX 3136         // 4*784
typedef unsigned long long ull;

// ---------------- scratch (device globals; no allocation) ----------------
__device__ __align__(16) float g_y1p[2][CIN * NPIX];  // conv1x1 ci-half partials
__device__ __align__(16) float g_s1p[2][CIN * NPIX];  // adder1x1 ci-half partial L1 sums
__device__ __align__(16) float g_p3 [6][CIN * NPIX];  // conv3x3 (kh,ciHalf) partials
__device__ __align__(16) float g_y3 [CIN * NPIX];     // conv3x3 combined
__device__ __align__(16) float g_p4 [6][CIN * NPIX];  // adder3x3 partials (+S)
// transposed weights: [ci][co] (plain float; duplicated at STS time)
__device__ __align__(16) float g_w1t [CIN * CIN];
__device__ __align__(16) float g_wa1t[CIN * CIN];
__device__ __align__(16) float g_w2t [9][CIN * CIN];
__device__ __align__(16) float g_wa2t[9][CIN * CIN];
// BN1 folded params
__device__ float g_sc1[CIN], g_sh1[CIN];

// ---------------- packed f32x2 helpers -----------------------------------
__device__ __forceinline__ ull fma2(ull a, ull b, ull c) {
    ull d; asm("fma.rn.f32x2 %0, %1, %2, %3;" : "=l"(d) : "l"(a), "l"(b), "l"(c)); return d;
}
__device__ __forceinline__ ull add2(ull a, ull b) {
    ull d; asm("add.rn.f32x2 %0, %1, %2;" : "=l"(d) : "l"(a), "l"(b)); return d;
}
#define NEG1X2 0xBF800000BF800000ULL
#define ABSM   0x7FFFFFFF7FFFFFFFULL

// =========================================================================
// kprep: transpose weights; fold BN1.
// =========================================================================
__global__ __launch_bounds__(256) void kprep(const float* __restrict__ w1,
                                             const float* __restrict__ wa1,
                                             const float* __restrict__ w2,
                                             const float* __restrict__ wa2,
                                             const float* __restrict__ g1,
                                             const float* __restrict__ b1,
                                             const float* __restrict__ m1,
                                             const float* __restrict__ v1) {
    int i = blockIdx.x * 256 + threadIdx.x;     // 64 blocks -> 16384
    int ci = i >> 7, co = i & 127;
    g_w1t [ci * CIN + co] = w1 [co * CIN + ci];
    g_wa1t[ci * CIN + co] = wa1[co * CIN + ci];
#pragma unroll
    for (int t = 0; t < 9; t++) {
        g_w2t [t][ci * CIN + co] = w2 [(co * CIN + ci) * 9 + t];
        g_wa2t[t][ci * CIN + co] = wa2[(co * CIN + ci) * 9 + t];
    }
    if (blockIdx.x == 0 && threadIdx.x < CIN) {
        int c = threadIdx.x;
        float sc = g1[c] / sqrtf(v1[c] + 1e-5f);
        g_sc1[c] = sc;
        g_sh1[c] = b1[c] - m1[c] * sc;
    }
}

// =========================================================================
// k1: conv1x1 ci-half partial. grid (2,49,2). CTA 64co x 64px, tile 4x4.
// =========================================================================
__global__ __launch_bounds__(256) void k1_conv1x1(const float* __restrict__ x) {
    __shared__ __align__(16) float  sA[2][16][64];
    __shared__ __align__(16) float2 sW[2][16][64];
    const int tid = threadIdx.x;
    const int col = tid & 15, row = tid >> 4;
    const int coBase = blockIdx.x * 64;
    const int qBase  = blockIdx.y * 64;
    const int ciBase = blockIdx.z * 64;

    ull acc[4][2];
#pragma unroll
    for (int i = 0; i < 4; i++) { acc[i][0] = 0; acc[i][1] = 0; }

    float aReg[4], wReg[4];
    auto ldg = [&](int s) {
        int ci0 = ciBase + (s << 4);
#pragma unroll
        for (int k = 0; k < 4; k++) {
            int e = k * 256 + tid;
            int q = qBase + (e & 63);
            int n = q / PP, p = q - n * PP;
            aReg[k] = x[(n * CIN + ci0 + (e >> 6)) * PP + p];
        }
#pragma unroll
        for (int k = 0; k < 4; k++) {
            int e = k * 256 + tid;
            wReg[k] = g_w1t[(ci0 + (e >> 6)) * CIN + coBase + (e & 63)];
        }
    };
    auto sts = [&](int b) {
#pragma unroll
        for (int k = 0; k < 4; k++) { int e = k * 256 + tid; sA[b][e >> 6][e & 63] = aReg[k]; }
#pragma unroll
        for (int k = 0; k < 4; k++) { int e = k * 256 + tid; sW[b][e >> 6][e & 63] = make_float2(wReg[k], wReg[k]); }
    };

    ldg(0); sts(0); __syncthreads();
    for (int s = 0; s < 4; s++) {
        int b = s & 1;
        if (s < 3) ldg(s + 1);
#pragma unroll
        for (int ci = 0; ci < 16; ci++) {
            ulonglong2 av = *(const ulonglong2*)&sA[b][ci][col * 4];
            ulonglong2 wp = *(const ulonglong2*)&sW[b][ci][row * 4];
            ulonglong2 wq = *(const ulonglong2*)&sW[b][ci][row * 4 + 2];
            acc[0][0] = fma2(wp.x, av.x, acc[0][0]); acc[0][1] = fma2(wp.x, av.y, acc[0][1]);
            acc[1][0] = fma2(wp.y, av.x, acc[1][0]); acc[1][1] = fma2(wp.y, av.y, acc[1][1]);
            acc[2][0] = fma2(wq.x, av.x, acc[2][0]); acc[2][1] = fma2(wq.x, av.y, acc[2][1]);
            acc[3][0] = fma2(wq.y, av.x, acc[3][0]); acc[3][1] = fma2(wq.y, av.y, acc[3][1]);
        }
        if (s < 3) sts(b ^ 1);
        __syncthreads();
    }
    const int q = qBase + col * 4;
    float* __restrict__ out = g_y1p[blockIdx.z];
#pragma unroll
    for (int i = 0; i < 4; i++) {
        int co = coBase + row * 4 + i;
        *(ull*)&out[co * NPIX + q]     = acc[i][0];
        *(ull*)&out[co * NPIX + q + 2] = acc[i][1];
    }
}

// =========================================================================
// k2: adder1x1 ci-half partial L1 sums. A = y1p[0]+y1p[1] at staging.
// =========================================================================
__global__ __launch_bounds__(256) void k2_adder1x1() {
    __shared__ __align__(16) float  sA[2][16][64];
    __shared__ __align__(16) float2 sW[2][16][64];
    const int tid = threadIdx.x;
    const int col = tid & 15, row = tid >> 4;
    const int coBase = blockIdx.x * 64;
    const int qBase  = blockIdx.y * 64;
    const int ciBase = blockIdx.z * 64;

    ull acc[4][2];
#pragma unroll
    for (int i = 0; i < 4; i++) { acc[i][0] = 0; acc[i][1] = 0; }

    float aReg[4], wReg[4];
    auto ldg = [&](int s) {
        int ci0 = ciBase + (s << 4);
#pragma unroll
        for (int k = 0; k < 4; k++) {
            int e = k * 256 + tid;
            int off = (ci0 + (e >> 6)) * NPIX + qBase + (e & 63);
            aReg[k] = g_y1p[0][off] + g_y1p[1][off];
        }
#pragma unroll
        for (int k = 0; k < 4; k++) {
            int e = k * 256 + tid;
            wReg[k] = g_wa1t[(ci0 + (e >> 6)) * CIN + coBase + (e & 63)];
        }
    };
    auto sts = [&](int b) {
#pragma unroll
        for (int k = 0; k < 4; k++) { int e = k * 256 + tid; sA[b][e >> 6][e & 63] = aReg[k]; }
#pragma unroll
        for (int k = 0; k < 4; k++) { int e = k * 256 + tid; sW[b][e >> 6][e & 63] = make_float2(wReg[k], wReg[k]); }
    };

    ldg(0); sts(0); __syncthreads();
    for (int s = 0; s < 4; s++) {
        int b = s & 1;
        if (s < 3) ldg(s + 1);
#pragma unroll
        for (int ci = 0; ci < 16; ci++) {
            ulonglong2 av = *(const ulonglong2*)&sA[b][ci][col * 4];
            ulonglong2 wp = *(const ulonglong2*)&sW[b][ci][row * 4];
            ulonglong2 wq = *(const ulonglong2*)&sW[b][ci][row * 4 + 2];
            acc[0][0] = add2(acc[0][0], fma2(wp.x, NEG1X2, av.x) & ABSM);
            acc[0][1] = add2(acc[0][1], fma2(wp.x, NEG1X2, av.y) & ABSM);
            acc[1][0] = add2(acc[1][0], fma2(wp.y, NEG1X2, av.x) & ABSM);
            acc[1][1] = add2(acc[1][1], fma2(wp.y, NEG1X2, av.y) & ABSM);
            acc[2][0] = add2(acc[2][0], fma2(wq.x, NEG1X2, av.x) & ABSM);
            acc[2][1] = add2(acc[2][1], fma2(wq.x, NEG1X2, av.y) & ABSM);
            acc[3][0] = add2(acc[3][0], fma2(wq.y, NEG1X2, av.x) & ABSM);
            acc[3][1] = add2(acc[3][1], fma2(wq.y, NEG1X2, av.y) & ABSM);
        }
        if (s < 3) sts(b ^ 1);
        __syncthreads();
    }
    const int q = qBase + col * 4;
    float* __restrict__ out = g_s1p[blockIdx.z];
#pragma unroll
    for (int i = 0; i < 4; i++) {
        int co = coBase + row * 4 + i;
        *(ull*)&out[co * NPIX + q]     = acc[i][0];
        *(ull*)&out[co * NPIX + q + 2] = acc[i][1];
    }
}

// =========================================================================
// k3/k4: 3x3 conv / adder. grid (2,49,6): z = kh*2 + ciHalf -> 588 CTAs.
// Conv (ADDER=false) fuses BN1+ReLU of the adder1x1 partials into A staging
// (z never materialized). Adder reads combined g_y3.
// =========================================================================
template <bool ADDER>
__global__ __launch_bounds__(256) void k3x3() {
    __shared__ __align__(16) float  sA[2][16][64];
    __shared__ __align__(16) float2 sW[2][16][64];
    __shared__ int sIdx[3][64];
    __shared__ float2 sBN[64];    // {scale, shift} for ci in [ciBase, ciBase+64)

    const int tid = threadIdx.x;
    const int col = tid & 15, row = tid >> 4;
    const int coBase = blockIdx.x * 64;
    const int qBase  = blockIdx.y * 64;
    const int kh     = blockIdx.z >> 1;
    const int ciBase = (blockIdx.z & 1) * 64;

    if (tid < 64) {
        int q = qBase + tid;
        int n = q / PP, p = q - n * PP;
        int h = p / 28, w = p - h * 28;
#pragma unroll
        for (int kw = 0; kw < 3; kw++) {
            int hh = h + kh - 1, ww = w + kw - 1;
            sIdx[kw][tid] = ((unsigned)hh < 28u && (unsigned)ww < 28u)
                          ? (n * PP + hh * 28 + ww) : -1;
        }
        if (!ADDER) sBN[tid] = make_float2(g_sc1[ciBase + tid], g_sh1[ciBase + tid]);
    }
    __syncthreads();

    ull acc[4][2];
#pragma unroll
    for (int i = 0; i < 4; i++) { acc[i][0] = 0; acc[i][1] = 0; }

    const float* __restrict__ wsrc = ADDER ? &g_wa2t[0][0] : &g_w2t[0][0];

    float aReg[4], wReg[4];
    auto ldg = [&](int s) {
        int kw = s >> 2, ciOff = (s & 3) << 4;
#pragma unroll
        for (int k = 0; k < 4; k++) {
            int e = k * 256 + tid;
            int ciL = ciOff + (e >> 6);                 // 0..63 within half
            int idx = sIdx[kw][e & 63];
            float v = 0.f;
            if (idx >= 0) {
                int off = (ciBase + ciL) * NPIX + idx;
                if (ADDER) {
                    v = g_y3[off];
                } else {
                    float ssum = g_s1p[0][off] + g_s1p[1][off];
                    float2 bn = sBN[ciL];
                    v = fmaxf(fmaf(-ssum, bn.x, bn.y), 0.f);
                }
            }
            aReg[k] = v;
        }
        const float* __restrict__ wslice = wsrc + (kh * 3 + kw) * (CIN * CIN);
#pragma unroll
        for (int k = 0; k < 4; k++) {
            int e = k * 256 + tid;
            wReg[k] = wslice[(ciBase + ciOff + (e >> 6)) * CIN + coBase + (e & 63)];
        }
    };
    auto sts = [&](int b) {
#pragma unroll
        for (int k = 0; k < 4; k++) { int e = k * 256 + tid; sA[b][e >> 6][e & 63] = aReg[k]; }
#pragma unroll
        for (int k = 0; k < 4; k++) { int e = k * 256 + tid; sW[b][e >> 6][e & 63] = make_float2(wReg[k], wReg[k]); }
    };

    ldg(0); sts(0); __syncthreads();
    for (int s = 0; s < 12; s++) {
        int b = s & 1;
        if (s < 11) ldg(s + 1);
#pragma unroll
        for (int ci = 0; ci < 16; ci++) {
            ulonglong2 av = *(const ulonglong2*)&sA[b][ci][col * 4];
            ulonglong2 wp = *(const ulonglong2*)&sW[b][ci][row * 4];
            ulonglong2 wq = *(const ulonglong2*)&sW[b][ci][row * 4 + 2];
            if (ADDER) {
                acc[0][0] = add2(acc[0][0], fma2(wp.x, NEG1X2, av.x) & ABSM);
                acc[0][1] = add2(acc[0][1], fma2(wp.x, NEG1X2, av.y) & ABSM);
                acc[1][0] = add2(acc[1][0], fma2(wp.y, NEG1X2, av.x) & ABSM);
                acc[1][1] = add2(acc[1][1], fma2(wp.y, NEG1X2, av.y) & ABSM);
                acc[2][0] = add2(acc[2][0], fma2(wq.x, NEG1X2, av.x) & ABSM);
                acc[2][1] = add2(acc[2][1], fma2(wq.x, NEG1X2, av.y) & ABSM);
                acc[3][0] = add2(acc[3][0], fma2(wq.y, NEG1X2, av.x) & ABSM);
                acc[3][1] = add2(acc[3][1], fma2(wq.y, NEG1X2, av.y) & ABSM);
            } else {
                acc[0][0] = fma2(wp.x, av.x, acc[0][0]); acc[0][1] = fma2(wp.x, av.y, acc[0][1]);
                acc[1][0] = fma2(wp.y, av.x, acc[1][0]); acc[1][1] = fma2(wp.y, av.y, acc[1][1]);
                acc[2][0] = fma2(wq.x, av.x, acc[2][0]); acc[2][1] = fma2(wq.x, av.y, acc[2][1]);
                acc[3][0] = fma2(wq.y, av.x, acc[3][0]); acc[3][1] = fma2(wq.y, av.y, acc[3][1]);
            }
        }
        if (s < 11) sts(b ^ 1);
        __syncthreads();
    }
    const int q = qBase + col * 4;
    float* __restrict__ out = ADDER ? g_p4[blockIdx.z] : g_p3[blockIdx.z];
#pragma unroll
    for (int i = 0; i < 4; i++) {
        int co = coBase + row * 4 + i;
        *(ull*)&out[co * NPIX + q]     = acc[i][0];
        *(ull*)&out[co * NPIX + q + 2] = acc[i][1];
    }
}

// ky: y3 = sum of 6 conv partials. 784 blocks x 128 thr, one float4 each.
__global__ __launch_bounds__(128) void ky() {
    int i = (blockIdx.x * 128 + threadIdx.x) * 4;
    float4 s = *(const float4*)&g_p3[0][i];
#pragma unroll
    for (int t = 1; t < 6; t++) {
        float4 a = *(const float4*)&g_p3[t][i];
        s.x += a.x; s.y += a.y; s.z += a.z; s.w += a.w;
    }
    *(float4*)&g_y3[i] = s;
}

// Epilogue: out = relu( relu(bn2(-S)) + x ), S = sum of 6 adder partials.
__device__ __forceinline__ float epi1(float S, float xv, float scale, float shift) {
    float v = fmaxf(fmaf(-S, scale, shift), 0.f);
    return fmaxf(v + xv, 0.f);
}
__global__ __launch_bounds__(128) void kepi(const float* __restrict__ x,
                                             const float* __restrict__ g2,
                                             const float* __restrict__ b2,
                                             const float* __restrict__ m2,
                                             const float* __restrict__ v2,
                                             float* __restrict__ out) {
    int base = (blockIdx.x * 128 + threadIdx.x) * 4;
    int c = base / NPIX;
    int q = base - c * NPIX;
    int n = q / PP, p = q - n * PP;
    float scale = g2[c] / sqrtf(v2[c] + 1e-5f);
    float shift = b2[c] - m2[c] * scale;
    float4 s = *(const float4*)&g_p4[0][base];
#pragma unroll
    for (int t = 1; t < 6; t++) {
        float4 a = *(const float4*)&g_p4[t][base];
        s.x += a.x; s.y += a.y; s.z += a.z; s.w += a.w;
    }
    int xi = (n * CIN + c) * PP + p;
    float4 xr = *(const float4*)&x[xi];
    float4 r;
    r.x = epi1(s.x, xr.x, scale, shift);
    r.y = epi1(s.y, xr.y, scale, shift);
    r.z = epi1(s.z, xr.z, scale, shift);
    r.w = epi1(s.w, xr.w, scale, shift);
    *(float4*)&out[xi] = r;
}

// =========================================================================
extern "C" void kernel_launch(void* const* d_in, const int* in_sizes, int n_in,
                              void* d_out, int out_size) {
    const float* x   = (const float*)d_in[0];
    const float* w1  = (const float*)d_in[1];
    const float* wa1 = (const float*)d_in[2];
    const float* g1  = (const float*)d_in[3];
    const float* b1  = (const float*)d_in[4];
    const float* m1  = (const float*)d_in[5];
    const float* v1  = (const float*)d_in[6];
    const float* w2  = (const float*)d_in[7];
    const float* wa2 = (const float*)d_in[8];
    const float* g2  = (const float*)d_in[9];
    const float* b2  = (const float*)d_in[10];
    const float* m2  = (const float*)d_in[11];
    const float* v2  = (const float*)d_in[12];
    float* out = (float*)d_out;

    kprep       <<<64,             256>>>(w1, wa1, w2, wa2, g1, b1, m1, v1);
    k1_conv1x1  <<<dim3(2, 49, 2), 256>>>(x);
    k2_adder1x1 <<<dim3(2, 49, 2), 256>>>();
    k3x3<false> <<<dim3(2, 49, 6), 256>>>();
    ky          <<<784,            128>>>();
    k3x3<true>  <<<dim3(2, 49, 6), 256>>>();
    kepi        <<<784,            128>>>(x, g2, b2, m2, v2, out);
}